// round 1
// baseline (speedup 1.0000x reference)
#include <cuda_runtime.h>

#define FULLMASK 0xffffffffu
#define IH 256
#define IW 192

// Gaussian taps for kernel_size=11, sigma=(11-1)/6, normalized (fp64-accurate,
// rounded to fp32). Indexed by |d|, d in [-5,5]. Static indices -> immediates.
static __device__ __forceinline__ float wt(int k) {
    const float t[6] = {0.23955940f, 0.20009682f, 0.11660614f,
                        0.04740849f, 0.01344761f, 0.00266126f};
    return t[k];
}

// One CTA (64 threads = 2 warps) per (b,k) image.
// Warp w produces blurred rows [w*128, w*128+128): lane owns 6 columns,
// hblur via shuffled halos, vblur via 11-slot rotating register accumulator.
__global__ __launch_bounds__(64, 8)
void dark_decode_kernel(const float* __restrict__ hm,
                        float* __restrict__ out, int n_img)
{
    const int img  = blockIdx.x;
    const int warp = threadIdx.x >> 5;
    const int lane = threadIdx.x & 31;
    const float* __restrict__ ip = hm + (long long)img * (IH * IW);
    const int base = warp * (IH / 2);   // output rows [base, base+128)
    const int col0 = lane * 6;

    float acc[11][6];
#pragma unroll
    for (int k = 0; k < 11; ++k)
#pragma unroll
        for (int c = 0; c < 6; ++c) acc[k][c] = 0.f;

    // prologue: load row (base-5) if it exists
    float2 cur0, cur1, cur2;
    {
        const int r0 = base - 5;
        if (r0 >= 0 && r0 < IH) {
            const float* rp = ip + r0 * IW + col0;
            cur0 = *(const float2*)(rp);
            cur1 = *(const float2*)(rp + 2);
            cur2 = *(const float2*)(rp + 4);
        } else {
            cur0 = make_float2(0.f, 0.f); cur1 = cur0; cur2 = cur0;
        }
    }

    float bestv  = -3.4e38f;
    int   bestlin = 0;

    // i = 0..137 ; row r = base-5+i ; output ro = base+i-10 completes at iter i
    for (int ib = 0; ib < 13; ++ib) {
#pragma unroll
        for (int u = 0; u < 11; ++u) {
            const int i = ib * 11 + u;
            if (i < 138) {
                const int r = base - 5 + i;

                // prefetch next row (hide DRAM latency behind this iter's FMAs)
                float2 nxt0, nxt1, nxt2;
                {
                    const int rn = r + 1;
                    if ((i + 1 < 138) && rn >= 0 && rn < IH) {
                        const float* rp = ip + rn * IW + col0;
                        nxt0 = *(const float2*)(rp);
                        nxt1 = *(const float2*)(rp + 2);
                        nxt2 = *(const float2*)(rp + 4);
                    } else {
                        nxt0 = make_float2(0.f, 0.f); nxt1 = nxt0; nxt2 = nxt0;
                    }
                }

                if (r >= 0 && r < IH) {
                    // extended segment e[0..15] = columns col0-5 .. col0+10 (zero-padded)
                    float e[16];
                    e[5] = cur0.x; e[6] = cur0.y; e[7] = cur1.x;
                    e[8] = cur1.y; e[9] = cur2.x; e[10] = cur2.y;
                    e[0]  = __shfl_up_sync(FULLMASK, e[6],  1);
                    e[1]  = __shfl_up_sync(FULLMASK, e[7],  1);
                    e[2]  = __shfl_up_sync(FULLMASK, e[8],  1);
                    e[3]  = __shfl_up_sync(FULLMASK, e[9],  1);
                    e[4]  = __shfl_up_sync(FULLMASK, e[10], 1);
                    e[11] = __shfl_down_sync(FULLMASK, e[5], 1);
                    e[12] = __shfl_down_sync(FULLMASK, e[6], 1);
                    e[13] = __shfl_down_sync(FULLMASK, e[7], 1);
                    e[14] = __shfl_down_sync(FULLMASK, e[8], 1);
                    e[15] = __shfl_down_sync(FULLMASK, e[9], 1);
                    if (lane == 0)  { e[0]=0.f; e[1]=0.f; e[2]=0.f; e[3]=0.f; e[4]=0.f; }
                    if (lane == 31) { e[11]=0.f; e[12]=0.f; e[13]=0.f; e[14]=0.f; e[15]=0.f; }

                    // horizontal blur: 6 outputs, taps d = -5..+5 (FFMA-imm chain)
                    float h[6];
#pragma unroll
                    for (int c = 0; c < 6; ++c) {
                        float s = e[c] * wt(5);
#pragma unroll
                        for (int d = 1; d <= 10; ++d)
                            s += e[c + d] * wt(d < 5 ? 5 - d : d - 5);
                        h[c] = s;
                    }

                    // vertical blur accumulation: slot (u+k)%11 is static
#pragma unroll
                    for (int k = 0; k < 11; ++k) {
                        const float wv = wt(k <= 5 ? 5 - k : k - 5);
                        const int slot = (u + k) % 11;
#pragma unroll
                        for (int c = 0; c < 6; ++c)
                            acc[slot][c] += h[c] * wv;
                    }
                }

                // emit completed output row ro = base+i-10 (slot u), recycle slot
                {
                    const int  ro = base + i - 10;
                    const bool em = (i >= 10);
#pragma unroll
                    for (int c = 0; c < 6; ++c) {
                        const float v = acc[u][c];
                        if (em && v > bestv) { bestv = v; bestlin = ro * IW + col0 + c; }
                        acc[u][c] = 0.f;
                    }
                }
                cur0 = nxt0; cur1 = nxt1; cur2 = nxt2;
            }
        }
    }

    // intra-warp argmax reduce (larger value wins; tie -> smaller linear index)
#pragma unroll
    for (int off = 16; off >= 1; off >>= 1) {
        const float ov = __shfl_xor_sync(FULLMASK, bestv, off);
        const int   oi = __shfl_xor_sync(FULLMASK, bestlin, off);
        if (ov > bestv || (ov == bestv && oi < bestlin)) { bestv = ov; bestlin = oi; }
    }

    __shared__ float s_v[2];
    __shared__ int   s_i[2];
    if (lane == 0) { s_v[warp] = bestv; s_i[warp] = bestlin; }
    __syncthreads();
    if (warp != 0) return;

    float fv; int fl;
    {
        const float v0 = s_v[0], v1 = s_v[1];
        const int   i0 = s_i[0], i1 = s_i[1];
        if (v1 > v0 || (v1 == v0 && i1 < i0)) { fv = v1; fl = i1; }
        else                                  { fv = v0; fl = i0; }
    }
    const int py = fl / IW;
    const int px = fl - py * IW;

    float offx = 0.f, offy = 0.f;
    const bool bok = (px >= 1) && (px < IW - 1) && (py >= 1) && (py < IH - 1);
    if (bok) {
        // 39 hblur values: flat j in [0,39), rr = py-6 + j/3, cc = px-1 + j%3
        float h0 = 0.f, h1 = 0.f;
        {
            int j = lane;
            int rr = py - 6 + j / 3;
            int cc = px - 1 + (j - (j / 3) * 3);
            if (rr >= 0 && rr < IH) {
                const float* rp = ip + rr * IW;
                float s = 0.f;
#pragma unroll
                for (int d = -5; d <= 5; ++d) {
                    const int c = cc + d;
                    float v = 0.f;
                    if ((unsigned)c < (unsigned)IW) v = rp[c];
                    s += v * wt(d < 0 ? -d : d);
                }
                h0 = s;
            }
            j = lane + 32;
            if (j < 39) {
                rr = py - 6 + j / 3;
                cc = px - 1 + (j - (j / 3) * 3);
                if (rr >= 0 && rr < IH) {
                    const float* rp = ip + rr * IW;
                    float s = 0.f;
#pragma unroll
                    for (int d = -5; d <= 5; ++d) {
                        const int c = cc + d;
                        float v = 0.f;
                        if ((unsigned)c < (unsigned)IW) v = rp[c];
                        s += v * wt(d < 0 ? -d : d);
                    }
                    h1 = s;
                }
            }
        }
        // lanes 0..8: vertical blur -> patch entry p(a,b), a=lane/3, b=lane%3
        const int a = lane / 3;
        const int b = lane - a * 3;
        float p = 0.f;
#pragma unroll
        for (int t = 0; t < 11; ++t) {
            const int j = (a + t) * 3 + b;
            const float va = __shfl_sync(FULLMASK, h0, j & 31);
            const float vb = __shfl_sync(FULLMASK, h1, j & 31);
            const float hv = (j < 32) ? va : vb;
            p += hv * wt(t <= 5 ? 5 - t : t - 5);
        }
        const float p00 = __shfl_sync(FULLMASK, p, 0);
        const float p01 = __shfl_sync(FULLMASK, p, 1);
        const float p02 = __shfl_sync(FULLMASK, p, 2);
        const float p10 = __shfl_sync(FULLMASK, p, 3);
        const float p11 = __shfl_sync(FULLMASK, p, 4);
        const float p12 = __shfl_sync(FULLMASK, p, 5);
        const float p20 = __shfl_sync(FULLMASK, p, 6);
        const float p21 = __shfl_sync(FULLMASK, p, 7);
        const float p22 = __shfl_sync(FULLMASK, p, 8);

        const float dx  = (p12 - p10) * 0.5f;
        const float dy  = (p21 - p01) * 0.5f;
        const float dxx = p12 - 2.f * p11 + p10;
        const float dyy = p21 - 2.f * p11 + p01;
        const float dxy = (p22 - p20 - p02 + p00) * 0.25f;
        const float det = dxx * dyy - dxy * dxy;
        if (fabsf(det) >= 1e-6f && dxx < 0.f) {
            const float ox = -(dyy * dx - dxy * dy) / det;
            const float oy = -(dxx * dy - dxy * dx) / det;
            offx = fminf(fmaxf(ox, -0.5f), 0.5f);
            offy = fminf(fmaxf(oy, -0.5f), 0.5f);
        }
    }

    if (lane == 0) {
        const float xo = fminf(fmaxf((float)px + offx, 0.f), (float)(IW - 1));
        const float yo = fminf(fmaxf((float)py + offy, 0.f), (float)(IH - 1));
        out[2 * img + 0] = xo;                       // coords[...,0] = x
        out[2 * img + 1] = yo;                       // coords[...,1] = y
        out[(long long)2 * n_img + img] = fv;        // max_vals
    }
}

extern "C" void kernel_launch(void* const* d_in, const int* in_sizes, int n_in,
                              void* d_out, int out_size)
{
    const float* hm = (const float*)d_in[0];
    // d_in[1] is kernel_size (always 11 in this problem; taps are baked in)
    const int n_img = in_sizes[0] / (IH * IW);
    dark_decode_kernel<<<n_img, 64>>>(hm, (float*)d_out, n_img);
}

// round 2
// speedup vs baseline: 1.1830x; 1.1830x over previous
#include <cuda_runtime.h>

#define FULLMASK 0xffffffffu
#define IH 256
#define IW 192

typedef unsigned long long u64;

// Gaussian taps for kernel_size=11, sigma=10/6, normalized. Indexed by |d|.
static __device__ __forceinline__ float wt(int k) {
    const float t[6] = {0.23955940f, 0.20009682f, 0.11660614f,
                        0.04740849f, 0.01344761f, 0.00266126f};
    return t[k];
}

static __device__ __forceinline__ u64 pk(float lo, float hi) {
    u64 r; asm("mov.b64 %0, {%1, %2};" : "=l"(r) : "f"(lo), "f"(hi)); return r;
}
static __device__ __forceinline__ void upk(u64 v, float& lo, float& hi) {
    asm("mov.b64 {%0, %1}, %2;" : "=f"(lo), "=f"(hi) : "l"(v));
}
static __device__ __forceinline__ u64 f2mul(u64 a, u64 b) {
    u64 d; asm("mul.rn.f32x2 %0, %1, %2;" : "=l"(d) : "l"(a), "l"(b)); return d;
}
static __device__ __forceinline__ u64 f2fma(u64 a, u64 b, u64 c) {
    u64 d; asm("fma.rn.f32x2 %0, %1, %2, %3;" : "=l"(d) : "l"(a), "l"(b), "l"(c)); return d;
}

// One CTA (64 threads = 2 warps) per (b,k) image.
// Warp w produces blurred rows [w*128, w*128+128): lane owns 6 columns,
// hblur via shuffled halos + packed f32x2 FMAs, vblur via 11-slot packed
// rotating register accumulator.
__global__ __launch_bounds__(64, 7)
void dark_decode_kernel(const float* __restrict__ hm,
                        float* __restrict__ out, int n_img)
{
    const int img  = blockIdx.x;
    const int warp = threadIdx.x >> 5;
    const int lane = threadIdx.x & 31;
    const float* __restrict__ ip = hm + (long long)img * (IH * IW);
    const int base = warp * (IH / 2);   // output rows [base, base+128)
    const int col0 = lane * 6;

    // packed weights (both halves equal), index = |d|
    u64 w2[6];
#pragma unroll
    for (int k = 0; k < 6; ++k) w2[k] = pk(wt(k), wt(k));

    // packed accumulators: 11 slots x 3 column-pairs
    u64 acc[11][3];
#pragma unroll
    for (int k = 0; k < 11; ++k)
#pragma unroll
        for (int c = 0; c < 3; ++c) acc[k][c] = 0ull;

    // prologue: load row (base-5) if it exists
    float2 cur0, cur1, cur2;
    {
        const int r0 = base - 5;
        if (r0 >= 0 && r0 < IH) {
            const float* rp = ip + r0 * IW + col0;
            cur0 = *(const float2*)(rp);
            cur1 = *(const float2*)(rp + 2);
            cur2 = *(const float2*)(rp + 4);
        } else {
            cur0 = make_float2(0.f, 0.f); cur1 = cur0; cur2 = cur0;
        }
    }

    float bestv   = -3.4e38f;
    int   bestlin = 0;

    // i = 0..137 ; row r = base-5+i ; output row ro = base+i-10 completes at i
    for (int ib = 0; ib < 13; ++ib) {
#pragma unroll
        for (int u = 0; u < 11; ++u) {
            const int i = ib * 11 + u;
            if (i < 138) {
                const int r = base - 5 + i;

                // prefetch next row
                float2 nxt0, nxt1, nxt2;
                {
                    const int rn = r + 1;
                    if ((i + 1 < 138) && rn >= 0 && rn < IH) {
                        const float* rp = ip + rn * IW + col0;
                        nxt0 = *(const float2*)(rp);
                        nxt1 = *(const float2*)(rp + 2);
                        nxt2 = *(const float2*)(rp + 4);
                    } else {
                        nxt0 = make_float2(0.f, 0.f); nxt1 = nxt0; nxt2 = nxt0;
                    }
                }

                if (r >= 0 && r < IH) {
                    // extended segment e[0..15] = cols col0-5 .. col0+10 (zero-padded)
                    float e[16];
                    e[5] = cur0.x; e[6] = cur0.y; e[7] = cur1.x;
                    e[8] = cur1.y; e[9] = cur2.x; e[10] = cur2.y;
                    e[0]  = __shfl_up_sync(FULLMASK, e[6],  1);
                    e[1]  = __shfl_up_sync(FULLMASK, e[7],  1);
                    e[2]  = __shfl_up_sync(FULLMASK, e[8],  1);
                    e[3]  = __shfl_up_sync(FULLMASK, e[9],  1);
                    e[4]  = __shfl_up_sync(FULLMASK, e[10], 1);
                    e[11] = __shfl_down_sync(FULLMASK, e[5], 1);
                    e[12] = __shfl_down_sync(FULLMASK, e[6], 1);
                    e[13] = __shfl_down_sync(FULLMASK, e[7], 1);
                    e[14] = __shfl_down_sync(FULLMASK, e[8], 1);
                    e[15] = __shfl_down_sync(FULLMASK, e[9], 1);
                    if (lane == 0)  { e[0]=0.f; e[1]=0.f; e[2]=0.f; e[3]=0.f; e[4]=0.f; }
                    if (lane == 31) { e[11]=0.f; e[12]=0.f; e[13]=0.f; e[14]=0.f; e[15]=0.f; }

                    // all adjacent pairs P[o] = (e[o], e[o+1]), o = 0..14
                    u64 P[15];
#pragma unroll
                    for (int o = 0; o < 15; ++o) P[o] = pk(e[o], e[o + 1]);

                    // horizontal blur, packed: h2[j] = (h[2j], h[2j+1])
                    // tap d -> weight wt(|d-5|); split even/odd d for shorter chains
                    u64 h2[3];
#pragma unroll
                    for (int j = 0; j < 3; ++j) {
                        u64 sa = f2mul(P[2*j + 0], w2[5]);      // d=0
                        sa = f2fma(P[2*j + 2],  w2[3], sa);     // d=2
                        sa = f2fma(P[2*j + 4],  w2[1], sa);     // d=4
                        sa = f2fma(P[2*j + 6],  w2[1], sa);     // d=6
                        sa = f2fma(P[2*j + 8],  w2[3], sa);     // d=8
                        sa = f2fma(P[2*j + 10], w2[5], sa);     // d=10
                        u64 sb = f2mul(P[2*j + 1], w2[4]);      // d=1
                        sb = f2fma(P[2*j + 3],  w2[2], sb);     // d=3
                        sb = f2fma(P[2*j + 5],  w2[0], sb);     // d=5
                        sb = f2fma(P[2*j + 7],  w2[2], sb);     // d=7
                        sb = f2fma(P[2*j + 9],  w2[4], sb);     // d=9
                        u64 s;
                        asm("add.rn.f32x2 %0, %1, %2;" : "=l"(s) : "l"(sa), "l"(sb));
                        h2[j] = s;
                    }

                    // vertical blur accumulation: slot (u+k)%11 is static
#pragma unroll
                    for (int k = 0; k < 11; ++k) {
                        const u64 wv = w2[k <= 5 ? 5 - k : k - 5];
                        const int slot = (u + k) % 11;
                        acc[slot][0] = f2fma(h2[0], wv, acc[slot][0]);
                        acc[slot][1] = f2fma(h2[1], wv, acc[slot][1]);
                        acc[slot][2] = f2fma(h2[2], wv, acc[slot][2]);
                    }
                }

                // emit completed output row ro = base+i-10 (slot u), recycle slot
                if (i >= 10) {
                    float a0, a1, a2, a3, a4, a5;
                    upk(acc[u][0], a0, a1);
                    upk(acc[u][1], a2, a3);
                    upk(acc[u][2], a4, a5);
                    const float m01 = fmaxf(a0, a1);
                    const float m23 = fmaxf(a2, a3);
                    const float m45 = fmaxf(a4, a5);
                    const float rowmax = fmaxf(fmaxf(m01, m23), m45);
                    if (rowmax > bestv) {        // rare
                        bestv = rowmax;
                        int c = 5;
                        if (a4 == rowmax) c = 4;
                        if (a3 == rowmax) c = 3;
                        if (a2 == rowmax) c = 2;
                        if (a1 == rowmax) c = 1;
                        if (a0 == rowmax) c = 0;
                        bestlin = (base + i - 10) * IW + col0 + c;
                    }
                }
                acc[u][0] = 0ull; acc[u][1] = 0ull; acc[u][2] = 0ull;

                cur0 = nxt0; cur1 = nxt1; cur2 = nxt2;
            }
        }
    }

    // intra-warp argmax reduce (larger value wins; tie -> smaller linear index)
#pragma unroll
    for (int off = 16; off >= 1; off >>= 1) {
        const float ov = __shfl_xor_sync(FULLMASK, bestv, off);
        const int   oi = __shfl_xor_sync(FULLMASK, bestlin, off);
        if (ov > bestv || (ov == bestv && oi < bestlin)) { bestv = ov; bestlin = oi; }
    }

    __shared__ float s_v[2];
    __shared__ int   s_i[2];
    if (lane == 0) { s_v[warp] = bestv; s_i[warp] = bestlin; }
    __syncthreads();
    if (warp != 0) return;

    float fv; int fl;
    {
        const float v0 = s_v[0], v1 = s_v[1];
        const int   i0 = s_i[0], i1 = s_i[1];
        if (v1 > v0 || (v1 == v0 && i1 < i0)) { fv = v1; fl = i1; }
        else                                  { fv = v0; fl = i0; }
    }
    const int py = fl / IW;
    const int px = fl - py * IW;

    float offx = 0.f, offy = 0.f;
    const bool bok = (px >= 1) && (px < IW - 1) && (py >= 1) && (py < IH - 1);
    if (bok) {
        // 39 hblur values: flat j in [0,39), rr = py-6 + j/3, cc = px-1 + j%3
        float h0 = 0.f, h1 = 0.f;
        {
            int j = lane;
            int rr = py - 6 + j / 3;
            int cc = px - 1 + (j - (j / 3) * 3);
            if (rr >= 0 && rr < IH) {
                const float* rp = ip + rr * IW;
                float s = 0.f;
#pragma unroll
                for (int d = -5; d <= 5; ++d) {
                    const int c = cc + d;
                    float v = 0.f;
                    if ((unsigned)c < (unsigned)IW) v = rp[c];
                    s += v * wt(d < 0 ? -d : d);
                }
                h0 = s;
            }
            j = lane + 32;
            if (j < 39) {
                rr = py - 6 + j / 3;
                cc = px - 1 + (j - (j / 3) * 3);
                if (rr >= 0 && rr < IH) {
                    const float* rp = ip + rr * IW;
                    float s = 0.f;
#pragma unroll
                    for (int d = -5; d <= 5; ++d) {
                        const int c = cc + d;
                        float v = 0.f;
                        if ((unsigned)c < (unsigned)IW) v = rp[c];
                        s += v * wt(d < 0 ? -d : d);
                    }
                    h1 = s;
                }
            }
        }
        // lanes 0..8: vertical blur -> patch entry p(a,b), a=lane/3, b=lane%3
        const int a = lane / 3;
        const int b = lane - a * 3;
        float p = 0.f;
#pragma unroll
        for (int t = 0; t < 11; ++t) {
            const int j = (a + t) * 3 + b;
            const float va = __shfl_sync(FULLMASK, h0, j & 31);
            const float vb = __shfl_sync(FULLMASK, h1, j & 31);
            const float hv = (j < 32) ? va : vb;
            p += hv * wt(t <= 5 ? 5 - t : t - 5);
        }
        const float p00 = __shfl_sync(FULLMASK, p, 0);
        const float p01 = __shfl_sync(FULLMASK, p, 1);
        const float p02 = __shfl_sync(FULLMASK, p, 2);
        const float p10 = __shfl_sync(FULLMASK, p, 3);
        const float p11 = __shfl_sync(FULLMASK, p, 4);
        const float p12 = __shfl_sync(FULLMASK, p, 5);
        const float p20 = __shfl_sync(FULLMASK, p, 6);
        const float p21 = __shfl_sync(FULLMASK, p, 7);
        const float p22 = __shfl_sync(FULLMASK, p, 8);

        const float dx  = (p12 - p10) * 0.5f;
        const float dy  = (p21 - p01) * 0.5f;
        const float dxx = p12 - 2.f * p11 + p10;
        const float dyy = p21 - 2.f * p11 + p01;
        const float dxy = (p22 - p20 - p02 + p00) * 0.25f;
        const float det = dxx * dyy - dxy * dxy;
        if (fabsf(det) >= 1e-6f && dxx < 0.f) {
            const float ox = -(dyy * dx - dxy * dy) / det;
            const float oy = -(dxx * dy - dxy * dx) / det;
            offx = fminf(fmaxf(ox, -0.5f), 0.5f);
            offy = fminf(fmaxf(oy, -0.5f), 0.5f);
        }
    }

    if (lane == 0) {
        const float xo = fminf(fmaxf((float)px + offx, 0.f), (float)(IW - 1));
        const float yo = fminf(fmaxf((float)py + offy, 0.f), (float)(IH - 1));
        out[2 * img + 0] = xo;                       // coords[...,0] = x
        out[2 * img + 1] = yo;                       // coords[...,1] = y
        out[(long long)2 * n_img + img] = fv;        // max_vals
    }
}

extern "C" void kernel_launch(void* const* d_in, const int* in_sizes, int n_in,
                              void* d_out, int out_size)
{
    const float* hm = (const float*)d_in[0];
    // d_in[1] is kernel_size (always 11 in this problem; taps are baked in)
    const int n_img = in_sizes[0] / (IH * IW);
    dark_decode_kernel<<<n_img, 64>>>(hm, (float*)d_out, n_img);
}